// round 2
// baseline (speedup 1.0000x reference)
#include <cuda_runtime.h>
#include <cuda_bf16.h>

#define N_NODES 50000
#define N_EDGES 640000
#define IN_CH 128
#define HID_CH 256

// Scratch (no cudaMalloc allowed): neighbor-sum accumulator + in-degree count.
__device__ float g_agg[N_NODES * IN_CH];
__device__ float g_cnt[N_NODES];

// ---------------------------------------------------------------------------
// Kernel 1: zero the accumulators (agg/cnt persist across graph replays, so
// they must be re-zeroed every launch for determinism).
// ---------------------------------------------------------------------------
__global__ void zero_kernel() {
    int idx = blockIdx.x * blockDim.x + threadIdx.x;
    int stride = gridDim.x * blockDim.x;
    const int total = N_NODES * IN_CH;
    for (int i = idx; i < total; i += stride) g_agg[i] = 0.0f;
    for (int i = idx; i < N_NODES; i += stride) g_cnt[i] = 0.0f;
}

// ---------------------------------------------------------------------------
// Kernel 2: per-edge scatter. One warp per edge; lane handles 4 channels.
// edge_index is int32 (JAX x64-disabled downcasts the reference's int64).
// ---------------------------------------------------------------------------
__global__ void scatter_kernel(const float* __restrict__ x,
                               const int* __restrict__ edge_index) {
    int warp = (blockIdx.x * blockDim.x + threadIdx.x) >> 5;
    int lane = threadIdx.x & 31;
    if (warp >= N_EDGES) return;

    int src = edge_index[warp];             // row 0: src
    int dst = edge_index[N_EDGES + warp];   // row 1: dst

    const float4* xrow = reinterpret_cast<const float4*>(x + (size_t)src * IN_CH);
    float4 v = xrow[lane];

    float* a = g_agg + (size_t)dst * IN_CH + lane * 4;
    atomicAdd(a + 0, v.x);
    atomicAdd(a + 1, v.y);
    atomicAdd(a + 2, v.z);
    atomicAdd(a + 3, v.w);

    if (lane == 0) atomicAdd(&g_cnt[dst], 1.0f);
}

// ---------------------------------------------------------------------------
// Kernel 3: fused mean + dual GEMM + bias.
// Block: 256 threads, thread t owns output column h = t. BN=8 nodes per block
// staged in shared memory (mean + self features). Node-data LDS are broadcast
// (same address across the warp -> conflict-free); weight LDGs are coalesced
// across h and L1/L2-resident. acc[8] register tile -> 16 FMA per k per thread.
// ---------------------------------------------------------------------------
#define BN 8

__global__ void __launch_bounds__(HID_CH)
gemm_kernel(const float* __restrict__ x,
            const float* __restrict__ W_l,
            const float* __restrict__ b_l,
            const float* __restrict__ W_r,
            float* __restrict__ out) {
    __shared__ float ms[BN][IN_CH];   // mean-aggregated neighbor features
    __shared__ float xs[BN][IN_CH];   // self features

    const int node0 = blockIdx.x * BN;
    const int tid = threadIdx.x;

    // Stage BN node rows (float4 granularity). 50000 % 8 == 0, no tail.
    for (int i = tid; i < BN * (IN_CH / 4); i += HID_CH) {
        int ni = i >> 5;          // node within tile
        int c = i & 31;           // float4 index within row
        int node = node0 + ni;
        float inv = 1.0f / fmaxf(g_cnt[node], 1.0f);
        float4 a = reinterpret_cast<const float4*>(g_agg + (size_t)node * IN_CH)[c];
        float4 xv = reinterpret_cast<const float4*>(x + (size_t)node * IN_CH)[c];
        reinterpret_cast<float4*>(&ms[ni][0])[c] =
            make_float4(a.x * inv, a.y * inv, a.z * inv, a.w * inv);
        reinterpret_cast<float4*>(&xs[ni][0])[c] = xv;
    }
    __syncthreads();

    const int h = tid;
    float acc[BN];
    const float bias = b_l[h];
#pragma unroll
    for (int i = 0; i < BN; i++) acc[i] = bias;

#pragma unroll 8
    for (int k = 0; k < IN_CH; k++) {
        float wl = W_l[k * HID_CH + h];
        float wr = W_r[k * HID_CH + h];
#pragma unroll
        for (int i = 0; i < BN; i++) {
            acc[i] += ms[i][k] * wl;
            acc[i] += xs[i][k] * wr;
        }
    }

#pragma unroll
    for (int i = 0; i < BN; i++) {
        out[(size_t)(node0 + i) * HID_CH + h] = acc[i];
    }
}

// ---------------------------------------------------------------------------
// Launch
// Inputs (metadata order): x [50000*128 f32], edge_index [2*640000 i32],
// W_l [128*256 f32], b_l [256 f32], W_r [128*256 f32].
// Output: [50000*256 f32].
// ---------------------------------------------------------------------------
extern "C" void kernel_launch(void* const* d_in, const int* in_sizes, int n_in,
                              void* d_out, int out_size) {
    const float* x = (const float*)d_in[0];
    const int* edge_index = (const int*)d_in[1];
    const float* W_l = (const float*)d_in[2];
    const float* b_l = (const float*)d_in[3];
    const float* W_r = (const float*)d_in[4];
    float* out = (float*)d_out;

    zero_kernel<<<592, 256>>>();

    // One warp per edge, 8 warps per block.
    scatter_kernel<<<(N_EDGES + 7) / 8, 256>>>(x, edge_index);

    gemm_kernel<<<N_NODES / BN, HID_CH>>>(x, W_l, b_l, W_r, out);
}

// round 4
// speedup vs baseline: 1.7830x; 1.7830x over previous
#include <cuda_runtime.h>
#include <cstdint>

#define N_NODES 50000
#define N_EDGES 640000
#define IN_CH   128
#define HID_CH  256
#define K_TOT   256
#define TILE_M  128
#define TILE_N  128
#define N_TILES 391             // ceil(50000/128)
#define CHUNK_K 32
#define N_CHUNKS 8
#define PAD     36              // floats per smem row (conflict-free fragments)

// Scratch (__device__ globals zero-initialized; pad rows of g_agg never written).
__device__ float g_agg[(N_TILES * TILE_M) * IN_CH];
__device__ float g_cnt[N_TILES * TILE_M];
__device__ float g_Bt[HID_CH * K_TOT];   // Bt[n][k] = Wcat[k][n], tf32-rounded

__device__ __forceinline__ uint32_t f2tf(float f) {
    uint32_t r;
    asm("cvt.rna.tf32.f32 %0, %1;" : "=r"(r) : "f"(f));
    return r;
}

// ---------------------------------------------------------------------------
// Kernel 1: zero accumulators.
// ---------------------------------------------------------------------------
__global__ void zero_kernel() {
    int idx = blockIdx.x * blockDim.x + threadIdx.x;
    int stride = gridDim.x * blockDim.x;
    const int total = N_NODES * IN_CH;
    for (int i = idx; i < total; i += stride) g_agg[i] = 0.0f;
    for (int i = idx; i < N_NODES; i += stride) g_cnt[i] = 0.0f;
}

// ---------------------------------------------------------------------------
// Kernel 2: per-edge scatter. One warp per edge; lane = 4 channels (float4).
// ---------------------------------------------------------------------------
__global__ void scatter_kernel(const float* __restrict__ x,
                               const int* __restrict__ edge_index) {
    int warp = (blockIdx.x * blockDim.x + threadIdx.x) >> 5;
    int lane = threadIdx.x & 31;
    if (warp >= N_EDGES) return;

    int src = edge_index[warp];
    int dst = edge_index[N_EDGES + warp];

    float4 v = reinterpret_cast<const float4*>(x + (size_t)src * IN_CH)[lane];
    float* a = g_agg + (size_t)dst * IN_CH + lane * 4;
    atomicAdd(a + 0, v.x);
    atomicAdd(a + 1, v.y);
    atomicAdd(a + 2, v.z);
    atomicAdd(a + 3, v.w);
    if (lane == 0) atomicAdd(&g_cnt[dst], 1.0f);
}

// ---------------------------------------------------------------------------
// Kernel 3: transpose W into K-major Bt[n][k], tf32-rounded.
// ---------------------------------------------------------------------------
__global__ void transpose_kernel(const float* __restrict__ W_l,
                                 const float* __restrict__ W_r) {
    int k = blockIdx.x;
    int n = threadIdx.x;
    float v = (k < IN_CH) ? W_l[k * HID_CH + n] : W_r[(k - IN_CH) * HID_CH + n];
    g_Bt[n * K_TOT + k] = __uint_as_float(f2tf(v));
}

// ---------------------------------------------------------------------------
// Kernel 4: tf32 mma.sync GEMM.
// Block 128x128 tile, grid (391, 2). 8 warps = 4(M) x 2(N); warp tile 32x64.
// K=256 in 8 chunks of 32, double-buffered smem, LDG-early overlap.
// A rows on the fly: k<128 -> g_agg*inv(cnt) (tf32), k>=128 -> x (tf32).
// ---------------------------------------------------------------------------
#define OFF_BIAS 0
#define OFF_A    512
#define ABYTES   (TILE_M * PAD * 4)        // 18432
#define OFF_B    (OFF_A + 2 * ABYTES)      // 37376
#define SMEM_BYTES (OFF_B + 2 * ABYTES)    // 74240

__device__ __forceinline__ void mma_tf32(float* c, const uint32_t* a,
                                         uint32_t b0, uint32_t b1) {
    asm("mma.sync.aligned.m16n8k8.row.col.f32.tf32.tf32.f32 "
        "{%0,%1,%2,%3}, {%4,%5,%6,%7}, {%8,%9}, {%0,%1,%2,%3};"
        : "+f"(c[0]), "+f"(c[1]), "+f"(c[2]), "+f"(c[3])
        : "r"(a[0]), "r"(a[1]), "r"(a[2]), "r"(a[3]), "r"(b0), "r"(b1));
}

__global__ void __launch_bounds__(256, 2)
gemm_kernel(const float* __restrict__ x,
            const float* __restrict__ b_l,
            float* __restrict__ out) {
    extern __shared__ char smem[];
    const int tid = threadIdx.x;
    const int wid = tid >> 5, lid = tid & 31;
    const int lrow = lid >> 2, lane4 = lid & 3;
    const int node0 = blockIdx.x * TILE_M;
    const int nblk0 = blockIdx.y * TILE_N;
    const int m_base = (wid & 3) * 32;
    const int n_base = (wid >> 2) * 64;

    float* bias_s = (float*)(smem + OFF_BIAS);
    if (tid < TILE_N) bias_s[tid] = b_l[nblk0 + tid];

    float4 aregs[4], bregs[4];
    int arow[4];

    // ---- chunk loader: LDG into registers (no smem writes) ----
    auto load_chunk = [&](int c) {
        const int kc = c * CHUNK_K;
        #pragma unroll
        for (int t = 0; t < 4; ++t) {
            int idx = tid + t * 256;        // 1024 float4 units for A
            int row = idx >> 3, j4 = idx & 7;
            int node = node0 + row;
            arow[t] = row * PAD + j4 * 4;
            float4 v;
            if (c < 4) {
                v = *reinterpret_cast<const float4*>(
                        g_agg + (size_t)node * IN_CH + kc + j4 * 4);
                float inv = 1.0f / fmaxf(g_cnt[node], 1.0f);
                v.x *= inv; v.y *= inv; v.z *= inv; v.w *= inv;
            } else if (node < N_NODES) {
                v = *reinterpret_cast<const float4*>(
                        x + (size_t)node * IN_CH + (kc - IN_CH) + j4 * 4);
            } else {
                v = make_float4(0.f, 0.f, 0.f, 0.f);
            }
            aregs[t] = v;
        }
        #pragma unroll
        for (int t = 0; t < 4; ++t) {       // 1024 float4 units for B
            int idx = tid + t * 256;
            int n = idx >> 3, j4 = idx & 7;
            bregs[t] = *reinterpret_cast<const float4*>(
                           g_Bt + (size_t)(nblk0 + n) * K_TOT + kc + j4 * 4);
        }
    };

    // ---- store staged registers into smem buffer (tf32-rounded A) ----
    auto sts_chunk = [&](int buf) {
        float* As = (float*)(smem + OFF_A + buf * ABYTES);
        float* Bs = (float*)(smem + OFF_B + buf * ABYTES);
        #pragma unroll
        for (int t = 0; t < 4; ++t) {
            float4 v = aregs[t];
            float2 lo = make_float2(__uint_as_float(f2tf(v.x)), __uint_as_float(f2tf(v.y)));
            float2 hi = make_float2(__uint_as_float(f2tf(v.z)), __uint_as_float(f2tf(v.w)));
            *reinterpret_cast<float2*>(As + arow[t]) = lo;
            *reinterpret_cast<float2*>(As + arow[t] + 2) = hi;
        }
        #pragma unroll
        for (int t = 0; t < 4; ++t) {
            int idx = tid + t * 256;
            int n = idx >> 3, j4 = idx & 7;
            float4 v = bregs[t];            // already tf32
            *reinterpret_cast<float2*>(Bs + n * PAD + j4 * 4) = make_float2(v.x, v.y);
            *reinterpret_cast<float2*>(Bs + n * PAD + j4 * 4 + 2) = make_float2(v.z, v.w);
        }
    };

    float acc[2][8][4];
    #pragma unroll
    for (int mi = 0; mi < 2; ++mi)
        #pragma unroll
        for (int ni = 0; ni < 8; ++ni)
            #pragma unroll
            for (int j = 0; j < 4; ++j) acc[mi][ni][j] = 0.f;

    load_chunk(0);
    sts_chunk(0);
    __syncthreads();

    for (int c = 0; c < N_CHUNKS; ++c) {
        const int buf = c & 1;
        if (c < N_CHUNKS - 1) load_chunk(c + 1);   // LDGs in flight over compute

        const float* As = (const float*)(smem + OFF_A + buf * ABYTES);
        const float* Bs = (const float*)(smem + OFF_B + buf * ABYTES);
        #pragma unroll
        for (int ks = 0; ks < 4; ++ks) {
            const int k0 = ks * 8;
            uint32_t a[2][4];
            #pragma unroll
            for (int mi = 0; mi < 2; ++mi) {
                const float* ap = As + (m_base + mi * 16 + lrow) * PAD + k0 + lane4;
                a[mi][0] = __float_as_uint(ap[0]);
                a[mi][1] = __float_as_uint(ap[8 * PAD]);
                a[mi][2] = __float_as_uint(ap[4]);
                a[mi][3] = __float_as_uint(ap[8 * PAD + 4]);
            }
            #pragma unroll
            for (int ni = 0; ni < 8; ++ni) {
                const float* bp = Bs + (n_base + ni * 8 + lrow) * PAD + k0 + lane4;
                uint32_t b0 = __float_as_uint(bp[0]);
                uint32_t b1 = __float_as_uint(bp[4]);
                mma_tf32(acc[0][ni], a[0], b0, b1);
                mma_tf32(acc[1][ni], a[1], b0, b1);
            }
        }

        if (c < N_CHUNKS - 1) {
            sts_chunk(buf ^ 1);
            __syncthreads();
        }
    }

    // ---- epilogue: bias + store (float2, 32B sectors filled per lane quad) ----
    #pragma unroll
    for (int mi = 0; mi < 2; ++mi) {
        int row = node0 + m_base + mi * 16 + lrow;
        #pragma unroll
        for (int ni = 0; ni < 8; ++ni) {
            int col = n_base + ni * 8 + lane4 * 2;
            float b0 = bias_s[col], b1 = bias_s[col + 1];
            if (row < N_NODES) {
                *reinterpret_cast<float2*>(out + (size_t)row * HID_CH + nblk0 + col) =
                    make_float2(acc[mi][ni][0] + b0, acc[mi][ni][1] + b1);
            }
            if (row + 8 < N_NODES) {
                *reinterpret_cast<float2*>(out + (size_t)(row + 8) * HID_CH + nblk0 + col) =
                    make_float2(acc[mi][ni][2] + b0, acc[mi][ni][3] + b1);
            }
        }
    }
}

// ---------------------------------------------------------------------------
// Launch. Inputs: x f32[50000*128], edge_index i32[2*640000],
// W_l f32[128*256], b_l f32[256], W_r f32[128*256]. Out f32[50000*256].
// ---------------------------------------------------------------------------
extern "C" void kernel_launch(void* const* d_in, const int* in_sizes, int n_in,
                              void* d_out, int out_size) {
    const float* x = (const float*)d_in[0];
    const int* edge_index = (const int*)d_in[1];
    const float* W_l = (const float*)d_in[2];
    const float* b_l = (const float*)d_in[3];
    const float* W_r = (const float*)d_in[4];
    float* out = (float*)d_out;

    cudaFuncSetAttribute(gemm_kernel,
                         cudaFuncAttributeMaxDynamicSharedMemorySize, SMEM_BYTES);

    zero_kernel<<<592, 256>>>();
    scatter_kernel<<<(N_EDGES + 7) / 8, 256>>>(x, edge_index);
    transpose_kernel<<<K_TOT, HID_CH>>>(W_l, W_r);

    dim3 grid(N_TILES, 2);
    gemm_kernel<<<grid, 256, SMEM_BYTES>>>(x, b_l, out);
}

// round 5
// speedup vs baseline: 2.9507x; 1.6549x over previous
#include <cuda_runtime.h>
#include <cstdint>

#define N_NODES 50000
#define N_EDGES 640000
#define IN_CH   128
#define HID_CH  256
#define K_TOT   256
#define TILE_M  128
#define TILE_N  128
#define N_TILES 391             // ceil(50000/128)
#define CHUNK_K 32
#define N_CHUNKS 8
#define PAD     36              // floats per smem row (conflict-free fragments)

// Scratch (__device__ globals zero-initialized; pad rows of g_agg never written).
__device__ float g_agg[(N_TILES * TILE_M) * IN_CH];
__device__ float g_cnt[N_TILES * TILE_M];
__device__ float g_Bt[HID_CH * K_TOT];   // Bt[n][k] = Wcat[k][n], tf32-rounded

__device__ __forceinline__ uint32_t f2tf(float f) {
    uint32_t r;
    asm("cvt.rna.tf32.f32 %0, %1;" : "=r"(r) : "f"(f));
    return r;
}

// ---------------------------------------------------------------------------
// Kernel 1: zero accumulators (float4 stores).
// ---------------------------------------------------------------------------
__global__ void zero_kernel() {
    int idx = blockIdx.x * blockDim.x + threadIdx.x;
    int stride = gridDim.x * blockDim.x;
    const int total4 = (N_NODES * IN_CH) / 4;
    float4 z = make_float4(0.f, 0.f, 0.f, 0.f);
    for (int i = idx; i < total4; i += stride)
        reinterpret_cast<float4*>(g_agg)[i] = z;
    for (int i = idx; i < N_NODES; i += stride) g_cnt[i] = 0.0f;
}

// ---------------------------------------------------------------------------
// Kernel 2: per-edge scatter. One warp per edge; lane = 4 channels.
// Vectorized reduction: one red.global.add.v4.f32 (16B) per lane.
// ---------------------------------------------------------------------------
__global__ void scatter_kernel(const float* __restrict__ x,
                               const int* __restrict__ edge_index) {
    int warp = (blockIdx.x * blockDim.x + threadIdx.x) >> 5;
    int lane = threadIdx.x & 31;
    if (warp >= N_EDGES) return;

    int src = edge_index[warp];
    int dst = edge_index[N_EDGES + warp];

    float4 v = reinterpret_cast<const float4*>(x + (size_t)src * IN_CH)[lane];
    float* a = g_agg + (size_t)dst * IN_CH + lane * 4;
    asm volatile("red.global.add.v4.f32 [%0], {%1, %2, %3, %4};"
                 :: "l"(a), "f"(v.x), "f"(v.y), "f"(v.z), "f"(v.w) : "memory");
    if (lane == 0) atomicAdd(&g_cnt[dst], 1.0f);
}

// ---------------------------------------------------------------------------
// Kernel 3: transpose W into K-major Bt[n][k], tf32-rounded.
// ---------------------------------------------------------------------------
__global__ void transpose_kernel(const float* __restrict__ W_l,
                                 const float* __restrict__ W_r) {
    int k = blockIdx.x;
    int n = threadIdx.x;
    float v = (k < IN_CH) ? W_l[k * HID_CH + n] : W_r[(k - IN_CH) * HID_CH + n];
    g_Bt[n * K_TOT + k] = __uint_as_float(f2tf(v));
}

// ---------------------------------------------------------------------------
// Kernel 4: tf32 mma.sync GEMM (unchanged from R4 — 67.7us, isolate scatter delta).
// Block 128x128 tile, grid (391, 2). 8 warps = 4(M) x 2(N); warp tile 32x64.
// ---------------------------------------------------------------------------
#define OFF_BIAS 0
#define OFF_A    512
#define ABYTES   (TILE_M * PAD * 4)        // 18432
#define OFF_B    (OFF_A + 2 * ABYTES)      // 37376
#define SMEM_BYTES (OFF_B + 2 * ABYTES)    // 74240

__device__ __forceinline__ void mma_tf32(float* c, const uint32_t* a,
                                         uint32_t b0, uint32_t b1) {
    asm("mma.sync.aligned.m16n8k8.row.col.f32.tf32.tf32.f32 "
        "{%0,%1,%2,%3}, {%4,%5,%6,%7}, {%8,%9}, {%0,%1,%2,%3};"
        : "+f"(c[0]), "+f"(c[1]), "+f"(c[2]), "+f"(c[3])
        : "r"(a[0]), "r"(a[1]), "r"(a[2]), "r"(a[3]), "r"(b0), "r"(b1));
}

__global__ void __launch_bounds__(256, 2)
gemm_kernel(const float* __restrict__ x,
            const float* __restrict__ b_l,
            float* __restrict__ out) {
    extern __shared__ char smem[];
    const int tid = threadIdx.x;
    const int wid = tid >> 5, lid = tid & 31;
    const int lrow = lid >> 2, lane4 = lid & 3;
    const int node0 = blockIdx.x * TILE_M;
    const int nblk0 = blockIdx.y * TILE_N;
    const int m_base = (wid & 3) * 32;
    const int n_base = (wid >> 2) * 64;

    float* bias_s = (float*)(smem + OFF_BIAS);
    if (tid < TILE_N) bias_s[tid] = b_l[nblk0 + tid];

    float4 aregs[4], bregs[4];
    int arow[4];

    auto load_chunk = [&](int c) {
        const int kc = c * CHUNK_K;
        #pragma unroll
        for (int t = 0; t < 4; ++t) {
            int idx = tid + t * 256;
            int row = idx >> 3, j4 = idx & 7;
            int node = node0 + row;
            arow[t] = row * PAD + j4 * 4;
            float4 v;
            if (c < 4) {
                v = *reinterpret_cast<const float4*>(
                        g_agg + (size_t)node * IN_CH + kc + j4 * 4);
                float inv = 1.0f / fmaxf(g_cnt[node], 1.0f);
                v.x *= inv; v.y *= inv; v.z *= inv; v.w *= inv;
            } else if (node < N_NODES) {
                v = *reinterpret_cast<const float4*>(
                        x + (size_t)node * IN_CH + (kc - IN_CH) + j4 * 4);
            } else {
                v = make_float4(0.f, 0.f, 0.f, 0.f);
            }
            aregs[t] = v;
        }
        #pragma unroll
        for (int t = 0; t < 4; ++t) {
            int idx = tid + t * 256;
            int n = idx >> 3, j4 = idx & 7;
            bregs[t] = *reinterpret_cast<const float4*>(
                           g_Bt + (size_t)(nblk0 + n) * K_TOT + kc + j4 * 4);
        }
    };

    auto sts_chunk = [&](int buf) {
        float* As = (float*)(smem + OFF_A + buf * ABYTES);
        float* Bs = (float*)(smem + OFF_B + buf * ABYTES);
        #pragma unroll
        for (int t = 0; t < 4; ++t) {
            float4 v = aregs[t];
            float2 lo = make_float2(__uint_as_float(f2tf(v.x)), __uint_as_float(f2tf(v.y)));
            float2 hi = make_float2(__uint_as_float(f2tf(v.z)), __uint_as_float(f2tf(v.w)));
            *reinterpret_cast<float2*>(As + arow[t]) = lo;
            *reinterpret_cast<float2*>(As + arow[t] + 2) = hi;
        }
        #pragma unroll
        for (int t = 0; t < 4; ++t) {
            int idx = tid + t * 256;
            int n = idx >> 3, j4 = idx & 7;
            float4 v = bregs[t];
            *reinterpret_cast<float2*>(Bs + n * PAD + j4 * 4) = make_float2(v.x, v.y);
            *reinterpret_cast<float2*>(Bs + n * PAD + j4 * 4 + 2) = make_float2(v.z, v.w);
        }
    };

    float acc[2][8][4];
    #pragma unroll
    for (int mi = 0; mi < 2; ++mi)
        #pragma unroll
        for (int ni = 0; ni < 8; ++ni)
            #pragma unroll
            for (int j = 0; j < 4; ++j) acc[mi][ni][j] = 0.f;

    load_chunk(0);
    sts_chunk(0);
    __syncthreads();

    for (int c = 0; c < N_CHUNKS; ++c) {
        const int buf = c & 1;
        if (c < N_CHUNKS - 1) load_chunk(c + 1);

        const float* As = (const float*)(smem + OFF_A + buf * ABYTES);
        const float* Bs = (const float*)(smem + OFF_B + buf * ABYTES);
        #pragma unroll
        for (int ks = 0; ks < 4; ++ks) {
            const int k0 = ks * 8;
            uint32_t a[2][4];
            #pragma unroll
            for (int mi = 0; mi < 2; ++mi) {
                const float* ap = As + (m_base + mi * 16 + lrow) * PAD + k0 + lane4;
                a[mi][0] = __float_as_uint(ap[0]);
                a[mi][1] = __float_as_uint(ap[8 * PAD]);
                a[mi][2] = __float_as_uint(ap[4]);
                a[mi][3] = __float_as_uint(ap[8 * PAD + 4]);
            }
            #pragma unroll
            for (int ni = 0; ni < 8; ++ni) {
                const float* bp = Bs + (n_base + ni * 8 + lrow) * PAD + k0 + lane4;
                uint32_t b0 = __float_as_uint(bp[0]);
                uint32_t b1 = __float_as_uint(bp[4]);
                mma_tf32(acc[0][ni], a[0], b0, b1);
                mma_tf32(acc[1][ni], a[1], b0, b1);
            }
        }

        if (c < N_CHUNKS - 1) {
            sts_chunk(buf ^ 1);
            __syncthreads();
        }
    }

    #pragma unroll
    for (int mi = 0; mi < 2; ++mi) {
        int row = node0 + m_base + mi * 16 + lrow;
        #pragma unroll
        for (int ni = 0; ni < 8; ++ni) {
            int col = n_base + ni * 8 + lane4 * 2;
            float b0 = bias_s[col], b1 = bias_s[col + 1];
            if (row < N_NODES) {
                *reinterpret_cast<float2*>(out + (size_t)row * HID_CH + nblk0 + col) =
                    make_float2(acc[mi][ni][0] + b0, acc[mi][ni][1] + b1);
            }
            if (row + 8 < N_NODES) {
                *reinterpret_cast<float2*>(out + (size_t)(row + 8) * HID_CH + nblk0 + col) =
                    make_float2(acc[mi][ni][2] + b0, acc[mi][ni][3] + b1);
            }
        }
    }
}

// ---------------------------------------------------------------------------
// Launch. Inputs: x f32[50000*128], edge_index i32[2*640000],
// W_l f32[128*256], b_l f32[256], W_r f32[128*256]. Out f32[50000*256].
// ---------------------------------------------------------------------------
extern "C" void kernel_launch(void* const* d_in, const int* in_sizes, int n_in,
                              void* d_out, int out_size) {
    const float* x = (const float*)d_in[0];
    const int* edge_index = (const int*)d_in[1];
    const float* W_l = (const float*)d_in[2];
    const float* b_l = (const float*)d_in[3];
    const float* W_r = (const float*)d_in[4];
    float* out = (float*)d_out;

    cudaFuncSetAttribute(gemm_kernel,
                         cudaFuncAttributeMaxDynamicSharedMemorySize, SMEM_BYTES);

    zero_kernel<<<592, 256>>>();
    scatter_kernel<<<(N_EDGES + 7) / 8, 256>>>(x, edge_index);
    transpose_kernel<<<K_TOT, HID_CH>>>(W_l, W_r);

    dim3 grid(N_TILES, 2);
    gemm_kernel<<<grid, 256, SMEM_BYTES>>>(x, b_l, out);
}